// round 8
// baseline (speedup 1.0000x reference)
#include <cuda_runtime.h>
#include <cuda_bf16.h>

#define N_WAVES 128
#define NPOLY 40          // high-freq waves -> exact-reduction poly path
#define FREQ_THR 1.05f    // any wave with f > this is forced onto the poly path
#define TPB 128

typedef unsigned long long u64;

__device__ __forceinline__ u64 pk(float lo, float hi) {
    u64 r; asm("mov.b64 %0, {%1, %2};" : "=l"(r) : "f"(lo), "f"(hi)); return r;
}
__device__ __forceinline__ void upk(u64 v, float& lo, float& hi) {
    asm("mov.b64 {%0, %1}, %2;" : "=f"(lo), "=f"(hi) : "l"(v));
}
__device__ __forceinline__ u64 pk32(unsigned lo, unsigned hi) {
    u64 r; asm("mov.b64 %0, {%1, %2};" : "=l"(r) : "r"(lo), "r"(hi)); return r;
}
__device__ __forceinline__ void upk32(u64 v, unsigned& lo, unsigned& hi) {
    asm("mov.b64 {%0, %1}, %2;" : "=r"(lo), "=r"(hi) : "l"(v));
}
__device__ __forceinline__ u64 fma2(u64 a, u64 b, u64 c) {
    u64 d; asm("fma.rn.f32x2 %0, %1, %2, %3;" : "=l"(d) : "l"(a), "l"(b), "l"(c)); return d;
}
__device__ __forceinline__ u64 mul2(u64 a, u64 b) {
    u64 d; asm("mul.rn.f32x2 %0, %1, %2;" : "=l"(d) : "l"(a), "l"(b)); return d;
}
__device__ __forceinline__ u64 add2(u64 a, u64 b) {
    u64 d; asm("add.rn.f32x2 %0, %1, %2;" : "=l"(d) : "l"(a), "l"(b)); return d;
}
__device__ __forceinline__ u64 sub2(u64 a, u64 b) {
    u64 d; asm("sub.rn.f32x2 %0, %1, %2;" : "=l"(d) : "l"(a), "l"(b)); return d;
}
__device__ __forceinline__ float sinap(float a) {
    float r; asm("sin.approx.f32 %0, %1;" : "=f"(r) : "f"(a)); return r;
}

// sin(pi*d), d in [-0.5, 0.5]: degree-7 odd minimax, coeffs folded to d-domain
#define A1F  3.14158197f
#define A3F -5.16714000f
#define A5F  2.54189000f
#define A7F -0.55461700f

__global__ void __launch_bounds__(TPB, 12)
wave_kernel(const float4* __restrict__ x4,   // 2 points per float4
            const float* __restrict__ freqs,
            const float* __restrict__ rots,
            const float* __restrict__ coeffs,
            float2* __restrict__ out2, int n) {
    // Wave slots [0, rawN): LOW-freq waves, params in RADIANS -> raw MUFU.SIN
    //   (3 fma-ops/pair: dot, dot, acc).
    // Wave slots [rawN, 128): HIGH-freq waves, params PRE-DOUBLED in cycles
    //   (half-cycle domain) -> exact range reduction + FMA-pipe polynomial.
    __shared__ float sf[N_WAVES];
    __shared__ ulonglong2 swp[2 * N_WAVES];
    __shared__ int s_rawN;

    int w = threadIdx.x;
    float f0v = 0.f;
    if (w < N_WAVES) { f0v = freqs[w]; sf[w] = f0v; }
    __syncthreads();

    if (w < N_WAVES) {
        // Deterministic rank (descending freq, tie-break by index) + high count.
        float fw = f0v;
        int rank = 0, nHigh = 0;
        for (int j = 0; j < N_WAVES; j++) {
            float fj = sf[j];
            rank  += (fj > fw) || (fj == fw && j < w);
            nHigh += (fj > FREQ_THR);
        }
        int polyN = (nHigh > NPOLY) ? nHigh : NPOLY;
        int rawN  = N_WAVES - polyN;
        if (w == 0) s_rawN = rawN;

        bool isPoly = (rank < polyN);
        int slot = isPoly ? (rawN + rank) : (rank - polyN);

        float r  = rots[w];
        float c0 = coeffs[2 * w];
        float c1 = coeffs[2 * w + 1];
        float sr, cr;
        sincosf(r, &sr, &cr);
        float A  = sqrtf(c0 * c0 + c1 * c1);
        float ph = atan2f(c1, c0);            // radians
        float gx, gy, p0;
        if (isPoly) {                          // half-cycle (v = 2u) domain
            gx = 2.f * fw * cr;
            gy = 2.f * fw * sr;
            p0 = ph * 0.3183098861837907f;     // ph / pi
        } else {                               // raw radian domain
            const float two_pi = 6.283185307179586f;
            gx = two_pi * fw * cr;
            gy = two_pi * fw * sr;
            p0 = ph;
        }
        ulonglong2 q0, q1;
        q0.x = pk(gx, gx); q0.y = pk(gy, gy);
        q1.x = pk(p0, p0); q1.y = pk(A, A);
        swp[2 * slot]     = q0;
        swp[2 * slot + 1] = q1;
    }
    __syncthreads();
    int rawN = s_rawN;

    int pairsTotal = n >> 1;
    int p = blockIdx.x * TPB + threadIdx.x;   // one float4 (pair of points) per thread

    float4 a = (p < pairsTotal) ? x4[p] : make_float4(0.f, 0.f, 0.f, 0.f);
    u64 px = pk(a.x, a.z), py = pk(a.y, a.w);
    u64 acc = pk(0.f, 0.f);

    const u64 MAG = pk(12582912.f, 12582912.f);    // 1.5 * 2^23
    const u64 PA1 = pk(A1F, A1F), PA3 = pk(A3F, A3F);
    const u64 PA5 = pk(A5F, A5F), PA7 = pk(A7F, A7F);

    // ---- raw-MUFU waves: low freq, phase fed directly in radians ----
#pragma unroll 4
    for (int w2 = 0; w2 < rawN; w2++) {
        ulonglong2 q0 = swp[2 * w2];
        ulonglong2 q1 = swp[2 * w2 + 1];
        u64 xr = fma2(px, q0.x, fma2(py, q0.y, q1.x));  // radians, |x| small
        float r0, r1; upk(xr, r0, r1);
        u64 s = pk(sinap(r0), sinap(r1));
        acc = fma2(q1.y, s, acc);
    }

    // ---- polynomial waves: exact range reduction, any freq ----
#pragma unroll 4
    for (int w2 = rawN; w2 < N_WAVES; w2++) {
        ulonglong2 q0 = swp[2 * w2];
        ulonglong2 q1 = swp[2 * w2 + 1];
        u64 v = fma2(px, q0.x, fma2(py, q0.y, q1.x));  // half-cycles (2u)
        u64 t = add2(v, MAG);             // mantissa bit0 = parity of rint(v)
        u64 nn = sub2(t, MAG);            // rint(v)
        u64 d = sub2(v, nn);              // [-0.5, 0.5]
        u64 s = mul2(d, d);
        u64 pl = fma2(PA7, s, PA5);
        pl = fma2(pl, s, PA3);
        pl = fma2(pl, s, PA1);
        u64 rr = mul2(pl, d);             // sin(pi*d)
        unsigned tl, th, rl, rh;
        upk32(t, tl, th); upk32(rr, rl, rh);
        rl ^= (tl << 31); rh ^= (th << 31);   // * (-1)^rint(v)  (ALU pipe)
        acc = fma2(q1.y, pk32(rl, rh), acc);
    }

    if (p < pairsTotal) {
        float o0, o1; upk(acc, o0, o1);
        out2[p] = make_float2(o0, o1);
    }

    // Odd-n tail: single scalar point.
    if ((n & 1) && blockIdx.x == 0 && threadIdx.x == 0) {
        float tx = ((const float2*)x4)[n - 1].x;
        float ty = ((const float2*)x4)[n - 1].y;
        float ac = 0.f;
        for (int w2 = 0; w2 < N_WAVES; w2++) {
            float gx, gxd, gy, gyd, ph, phd, A, Ad;
            upk(swp[2 * w2].x, gx, gxd);
            upk(swp[2 * w2].y, gy, gyd);
            upk(swp[2 * w2 + 1].x, ph, phd);
            upk(swp[2 * w2 + 1].y, A, Ad);
            if (w2 < rawN) {                   // radian params, low freq
                float u = fmaf(tx, gx, fmaf(ty, gy, ph));
                ac = fmaf(A, sinap(u), ac);
            } else {                           // half-cycle params
                float v = fmaf(tx, gx, fmaf(ty, gy, ph));
                float nn = rintf(v);
                float d = v - nn;
                float sv = sinap(3.14159265f * d);
                if (((int)nn) & 1) sv = -sv;
                ac = fmaf(A, sv, ac);
            }
        }
        ((float*)out2)[n - 1] = ac;
    }
}

extern "C" void kernel_launch(void* const* d_in, const int* in_sizes, int n_in,
                              void* d_out, int out_size) {
    const float* x      = (const float*)d_in[0];  // [N,2]
    const float* freqs  = (const float*)d_in[1];  // [W,1]
    const float* rots   = (const float*)d_in[2];  // [W,1]
    const float* coeffs = (const float*)d_in[3];  // [W,2]
    float* out = (float*)d_out;                   // [N,1]

    int n = in_sizes[0] / 2;

    int pairs = (n + 1) / 2;
    int blocks = (pairs + TPB - 1) / TPB;
    wave_kernel<<<blocks, TPB>>>((const float4*)x, freqs, rots, coeffs,
                                 (float2*)out, n);
}

// round 9
// speedup vs baseline: 1.0884x; 1.0884x over previous
#include <cuda_runtime.h>
#include <cuda_bf16.h>

#define N_WAVES 128
#define POLYN 40          // top-POLYN waves by freq -> exact-reduction poly path
#define RAWN (N_WAVES - POLYN)   // 88 low-freq waves -> raw-radian MUFU path
#define TPB 128

typedef unsigned long long u64;

__device__ __forceinline__ u64 pk(float lo, float hi) {
    u64 r; asm("mov.b64 %0, {%1, %2};" : "=l"(r) : "f"(lo), "f"(hi)); return r;
}
__device__ __forceinline__ void upk(u64 v, float& lo, float& hi) {
    asm("mov.b64 {%0, %1}, %2;" : "=f"(lo), "=f"(hi) : "l"(v));
}
__device__ __forceinline__ u64 pk32(unsigned lo, unsigned hi) {
    u64 r; asm("mov.b64 %0, {%1, %2};" : "=l"(r) : "r"(lo), "r"(hi)); return r;
}
__device__ __forceinline__ void upk32(u64 v, unsigned& lo, unsigned& hi) {
    asm("mov.b64 {%0, %1}, %2;" : "=r"(lo), "=r"(hi) : "l"(v));
}
__device__ __forceinline__ u64 fma2(u64 a, u64 b, u64 c) {
    u64 d; asm("fma.rn.f32x2 %0, %1, %2, %3;" : "=l"(d) : "l"(a), "l"(b), "l"(c)); return d;
}
__device__ __forceinline__ u64 mul2(u64 a, u64 b) {
    u64 d; asm("mul.rn.f32x2 %0, %1, %2;" : "=l"(d) : "l"(a), "l"(b)); return d;
}
__device__ __forceinline__ u64 add2(u64 a, u64 b) {
    u64 d; asm("add.rn.f32x2 %0, %1, %2;" : "=l"(d) : "l"(a), "l"(b)); return d;
}
__device__ __forceinline__ u64 sub2(u64 a, u64 b) {
    u64 d; asm("sub.rn.f32x2 %0, %1, %2;" : "=l"(d) : "l"(a), "l"(b)); return d;
}
__device__ __forceinline__ float sinap(float a) {
    float r; asm("sin.approx.f32 %0, %1;" : "=f"(r) : "f"(a)); return r;
}

// sin(pi*d), d in [-0.5, 0.5]: degree-7 odd minimax, coeffs folded to d-domain
#define A1F  3.14158197f
#define A3F -5.16714000f
#define A5F  2.54189000f
#define A7F -0.55461700f

__global__ void __launch_bounds__(TPB, 12)
wave_kernel(const float4* __restrict__ x4,   // 2 points per float4
            const float* __restrict__ freqs,
            const float* __restrict__ rots,
            const float* __restrict__ coeffs,
            float2* __restrict__ out2, int n) {
    // Slots [0, RAWN): low-freq waves, params in RADIANS -> raw MUFU.SIN
    //   (2 fma2 dot + 1 fma2 acc per pair).
    // Slots [RAWN, 128): top-POLYN-by-freq waves, params PRE-DOUBLED in cycles
    //   (half-cycle domain) -> exact range reduction + FMA-pipe polynomial.
    __shared__ float sf[N_WAVES];
    __shared__ ulonglong2 swp[2 * N_WAVES];

    int w = threadIdx.x;
    float fw = 0.f;
    if (w < N_WAVES) { fw = freqs[w]; sf[w] = fw; }
    __syncthreads();

    if (w < N_WAVES) {
        // Deterministic rank (descending freq, tie-break by index).
        int rank = 0;
        for (int j = 0; j < N_WAVES; j++) {
            float fj = sf[j];
            rank += (fj > fw) || (fj == fw && j < w);
        }
        bool isPoly = (rank < POLYN);
        int slot = isPoly ? (RAWN + rank) : (rank - POLYN);

        float r  = rots[w];
        float c0 = coeffs[2 * w];
        float c1 = coeffs[2 * w + 1];
        float sr, cr;
        sincosf(r, &sr, &cr);
        float A  = sqrtf(c0 * c0 + c1 * c1);
        float ph = atan2f(c1, c0);            // radians
        float gx, gy, p0;
        if (isPoly) {                          // half-cycle (v = 2u) domain
            gx = 2.f * fw * cr;
            gy = 2.f * fw * sr;
            p0 = ph * 0.3183098861837907f;     // ph / pi
        } else {                               // raw radian domain
            const float two_pi = 6.283185307179586f;
            gx = two_pi * fw * cr;
            gy = two_pi * fw * sr;
            p0 = ph;
        }
        ulonglong2 q0, q1;
        q0.x = pk(gx, gx); q0.y = pk(gy, gy);
        q1.x = pk(p0, p0); q1.y = pk(A, A);
        swp[2 * slot]     = q0;
        swp[2 * slot + 1] = q1;
    }
    __syncthreads();

    int pairsTotal = n >> 1;
    int p = blockIdx.x * TPB + threadIdx.x;   // one float4 (pair of points) per thread

    float4 a = (p < pairsTotal) ? x4[p] : make_float4(0.f, 0.f, 0.f, 0.f);
    u64 px = pk(a.x, a.z), py = pk(a.y, a.w);
    u64 acc = pk(0.f, 0.f);

    const u64 MAG = pk(12582912.f, 12582912.f);    // 1.5 * 2^23
    const u64 PA1 = pk(A1F, A1F), PA3 = pk(A3F, A3F);
    const u64 PA5 = pk(A5F, A5F), PA7 = pk(A7F, A7F);

    // ---- raw-MUFU waves: low freq, phase fed directly in radians ----
#pragma unroll 4
    for (int w2 = 0; w2 < RAWN; w2++) {
        ulonglong2 q0 = swp[2 * w2];
        ulonglong2 q1 = swp[2 * w2 + 1];
        u64 xr = fma2(px, q0.x, fma2(py, q0.y, q1.x));  // radians, |x| <= ~10
        float r0, r1; upk(xr, r0, r1);
        u64 s = pk(sinap(r0), sinap(r1));
        acc = fma2(q1.y, s, acc);
    }

    // ---- polynomial waves: exact range reduction, any freq ----
#pragma unroll 4
    for (int w2 = RAWN; w2 < N_WAVES; w2++) {
        ulonglong2 q0 = swp[2 * w2];
        ulonglong2 q1 = swp[2 * w2 + 1];
        u64 v = fma2(px, q0.x, fma2(py, q0.y, q1.x));  // half-cycles (2u)
        u64 t = add2(v, MAG);             // mantissa bit0 = parity of rint(v)
        u64 nn = sub2(t, MAG);            // rint(v)
        u64 d = sub2(v, nn);              // [-0.5, 0.5]
        u64 s = mul2(d, d);
        u64 pl = fma2(PA7, s, PA5);
        pl = fma2(pl, s, PA3);
        pl = fma2(pl, s, PA1);
        u64 rr = mul2(pl, d);             // sin(pi*d)
        unsigned tl, th, rl, rh;
        upk32(t, tl, th); upk32(rr, rl, rh);
        rl ^= (tl << 31); rh ^= (th << 31);   // * (-1)^rint(v)  (ALU pipe)
        acc = fma2(q1.y, pk32(rl, rh), acc);
    }

    if (p < pairsTotal) {
        float o0, o1; upk(acc, o0, o1);
        out2[p] = make_float2(o0, o1);
    }

    // Odd-n tail: single scalar point.
    if ((n & 1) && blockIdx.x == 0 && threadIdx.x == 0) {
        float tx = ((const float2*)x4)[n - 1].x;
        float ty = ((const float2*)x4)[n - 1].y;
        float ac = 0.f;
        for (int w2 = 0; w2 < N_WAVES; w2++) {
            float gx, gxd, gy, gyd, ph, phd, A, Ad;
            upk(swp[2 * w2].x, gx, gxd);
            upk(swp[2 * w2].y, gy, gyd);
            upk(swp[2 * w2 + 1].x, ph, phd);
            upk(swp[2 * w2 + 1].y, A, Ad);
            if (w2 < RAWN) {                   // radian params, low freq
                float u = fmaf(tx, gx, fmaf(ty, gy, ph));
                ac = fmaf(A, sinap(u), ac);
            } else {                           // half-cycle params
                float v = fmaf(tx, gx, fmaf(ty, gy, ph));
                float nn = rintf(v);
                float d = v - nn;
                float sv = sinap(3.14159265f * d);
                if (((int)nn) & 1) sv = -sv;
                ac = fmaf(A, sv, ac);
            }
        }
        ((float*)out2)[n - 1] = ac;
    }
}

extern "C" void kernel_launch(void* const* d_in, const int* in_sizes, int n_in,
                              void* d_out, int out_size) {
    const float* x      = (const float*)d_in[0];  // [N,2]
    const float* freqs  = (const float*)d_in[1];  // [W,1]
    const float* rots   = (const float*)d_in[2];  // [W,1]
    const float* coeffs = (const float*)d_in[3];  // [W,2]
    float* out = (float*)d_out;                   // [N,1]

    int n = in_sizes[0] / 2;

    int pairs = (n + 1) / 2;
    int blocks = (pairs + TPB - 1) / TPB;
    wave_kernel<<<blocks, TPB>>>((const float4*)x, freqs, rots, coeffs,
                                 (float2*)out, n);
}